// round 3
// baseline (speedup 1.0000x reference)
#include <cuda_runtime.h>

// NaiveTemporalShift: x[B,T,N,C] fp32, U=1 -> channel partitions [0,86,171,256)
// with temporal shifts [-1, 0, +1]. out[b,t,n,c] = x[b, t-s(c), n, c] or 0.
//
// R2: 8 float4 per thread (streams split along B, stride TOTAL4/8, all sharing
// t and c4) -> 8-read burst then 8-write burst for better DRAM bus turnaround;
// boundary chunks (c4==21, c4==42) handled by a 1-extra-vector-load blend
// instead of 16 divergent scalar loads.

#define TS_B 64
#define TS_T 128
#define TS_N 21
#define TS_C 256
#define TS_NC4  (TS_N * TS_C / 4)                  // 1344 float4 per (b,t)
#define TS_TOTAL4 (TS_B * TS_T * TS_N * TS_C / 4)  // 11,010,048 float4
#define TS_Q (TS_TOTAL4 / 8)                       // 1,376,256 (8 b's of float4)

__global__ void __launch_bounds__(256)
temporal_shift_kernel(const float* __restrict__ xf, float* __restrict__ outf) {
    int idx = blockIdx.x * 256 + threadIdx.x;   // in [0, TS_Q)

    const float4* __restrict__ x4 = reinterpret_cast<const float4*>(xf);
    float4* __restrict__ o4 = reinterpret_cast<float4*>(outf);

    unsigned row = (unsigned)idx >> 6;            // (b*T + t)*N + n, b in [0,8)
    int c4 = idx & 63;                            // float4 chunk within C=256
    int t = (int)((row / TS_N) & (TS_T - 1));     // shared by all 8 replicas

    // Primary (shifted) source offset and its zero-fill predicate.
    // c4 <= 21 : shift -1 (read t+1), zero at t == T-1  (chunk 21: comps 0,1)
    // 22..41   : copy (del = 0)
    // c4 >= 42 : shift +1 (read t-1), zero at t == 0    (chunk 42: comp 3)
    int del;
    bool zero;
    if (c4 <= 21)      { del =  TS_NC4; zero = (t == TS_T - 1); }
    else if (c4 >= 42) { del = -TS_NC4; zero = (t == 0);        }
    else               { del = 0;       zero = false;           }

    const bool bndLo = (c4 == 21);   // comps 2,3 come from unshifted
    const bool bndHi = (c4 == 42);   // comps 0,1,2 come from unshifted

    const float4 zv = make_float4(0.f, 0.f, 0.f, 0.f);
    float4 m[8];

    // 8-read burst (independent streams, MLP_p1 = 8)
    #pragma unroll
    for (int k = 0; k < 8; k++)
        m[k] = zero ? zv : __ldcs(x4 + idx + k * TS_Q + del);

    // Boundary blend: one lane per warp, one extra vector load per stream.
    if (bndLo) {
        #pragma unroll
        for (int k = 0; k < 8; k++) {
            float4 p = __ldcs(x4 + idx + k * TS_Q);
            m[k].z = p.z; m[k].w = p.w;
        }
    } else if (bndHi) {
        #pragma unroll
        for (int k = 0; k < 8; k++) {
            float4 p = __ldcs(x4 + idx + k * TS_Q);
            m[k].x = p.x; m[k].y = p.y; m[k].z = p.z;
        }
    }

    // 8-write burst
    #pragma unroll
    for (int k = 0; k < 8; k++)
        __stcs(o4 + idx + k * TS_Q, m[k]);
}

extern "C" void kernel_launch(void* const* d_in, const int* in_sizes, int n_in,
                              void* d_out, int out_size) {
    const float* x = (const float*)d_in[0];
    float* out = (float*)d_out;
    int blocks = TS_Q / 256;   // 5376, exact
    temporal_shift_kernel<<<blocks, 256>>>(x, out);
}

// round 4
// speedup vs baseline: 1.0143x; 1.0143x over previous
#include <cuda_runtime.h>

// NaiveTemporalShift: x[B,T,N,C] fp32, U=1 -> channel partitions [0,86,171,256)
// with temporal shifts [-1, 0, +1]. out[b,t,n,c] = x[b, t-s(c), n, c] or 0.
//
// R3: 4 float4 per thread (streams split along B, stride TOTAL4/4, all sharing
// t and c4). PLAIN cache policy (no .cs streaming hints) so L2 batches dirty
// writebacks on its own schedule; boundary chunks handled by vector blend;
// 512-thread blocks, ~30 regs -> full occupancy ceiling.

#define TS_B 64
#define TS_T 128
#define TS_N 21
#define TS_C 256
#define TS_NC4  (TS_N * TS_C / 4)                  // 1344 float4 per (b,t)
#define TS_TOTAL4 (TS_B * TS_T * TS_N * TS_C / 4)  // 11,010,048 float4
#define TS_Q (TS_TOTAL4 / 4)                       // 2,752,512 (16 b's of float4)

__global__ void __launch_bounds__(512)
temporal_shift_kernel(const float* __restrict__ xf, float* __restrict__ outf) {
    int idx = blockIdx.x * 512 + threadIdx.x;   // in [0, TS_Q)

    const float4* __restrict__ x4 = reinterpret_cast<const float4*>(xf);
    float4* __restrict__ o4 = reinterpret_cast<float4*>(outf);

    unsigned row = (unsigned)idx >> 6;            // (b*T + t)*N + n, b in [0,16)
    int c4 = idx & 63;                            // float4 chunk within C=256
    int t = (int)((row / TS_N) & (TS_T - 1));     // shared by all 4 replicas

    // Primary (shifted) source offset and zero-fill predicate.
    // c4 <= 21 : shift -1 (read t+1), zero at t == T-1  (chunk 21: comps 0,1)
    // 22..41   : copy (del = 0)
    // c4 >= 42 : shift +1 (read t-1), zero at t == 0    (chunk 42: comp 3)
    int del;
    bool zero;
    if (c4 <= 21)      { del =  TS_NC4; zero = (t == TS_T - 1); }
    else if (c4 >= 42) { del = -TS_NC4; zero = (t == 0);        }
    else               { del = 0;       zero = false;           }

    const bool bndLo = (c4 == 21);   // comps 2,3 come from unshifted (copy)
    const bool bndHi = (c4 == 42);   // comps 0,1,2 come from unshifted (copy)

    const float4 zv = make_float4(0.f, 0.f, 0.f, 0.f);
    float4 m[4];

    // 4 independent shifted reads
    #pragma unroll
    for (int k = 0; k < 4; k++)
        m[k] = zero ? zv : x4[idx + k * TS_Q + del];

    // Boundary blend: one lane per warp does one extra vector read per stream.
    // Applies regardless of `zero` (the copy components are always valid).
    if (bndLo) {
        #pragma unroll
        for (int k = 0; k < 4; k++) {
            float4 p = x4[idx + k * TS_Q];
            m[k].z = p.z; m[k].w = p.w;
        }
    } else if (bndHi) {
        #pragma unroll
        for (int k = 0; k < 4; k++) {
            float4 p = x4[idx + k * TS_Q];
            m[k].x = p.x; m[k].y = p.y; m[k].z = p.z;
        }
    }

    // 4 writes
    #pragma unroll
    for (int k = 0; k < 4; k++)
        o4[idx + k * TS_Q] = m[k];
}

extern "C" void kernel_launch(void* const* d_in, const int* in_sizes, int n_in,
                              void* d_out, int out_size) {
    const float* x = (const float*)d_in[0];
    float* out = (float*)d_out;
    int blocks = TS_Q / 512;   // 5376, exact
    temporal_shift_kernel<<<blocks, 512>>>(x, out);
}